// round 5
// baseline (speedup 1.0000x reference)
#include <cuda_runtime.h>
#include <math.h>

#define Bz 64
#define Tz 256
#define Fz 512
#define Hz 1024
#define Oz 512

typedef unsigned long long ULL;

// Persistent device state (transposed layouts: [feature][batch])
__device__ __align__(16) float g_hT[2][Hz * Bz];   // hidden state ping-pong, [j][b]
__device__ __align__(16) float g_cinT[Fz * Bz];    // masked input, [f][b]
__device__ int g_nsel;

__device__ __forceinline__ float sigmf(float v) { return 1.0f / (1.0f + expf(-v)); }

// ---- packed f32x2 helpers (Blackwell FFMA2 path) ----
__device__ __forceinline__ void ffma2(ULL& d, ULL a, ULL b) {
    asm("fma.rn.f32x2 %0, %1, %2, %0;" : "+l"(d) : "l"(a), "l"(b));
}
__device__ __forceinline__ void fadd2(ULL& d, ULL a) {
    asm("add.rn.f32x2 %0, %0, %1;" : "+l"(d) : "l"(a));
}
__device__ __forceinline__ ULL dup2(float w) {
    unsigned int u = __float_as_uint(w); ULL r;
    asm("mov.b64 %0, {%1, %1};" : "=l"(r) : "r"(u));
    return r;
}
__device__ __forceinline__ void unpk(ULL v, float& lo, float& hi) {
    unsigned int a, b;
    asm("mov.b64 {%0, %1}, %2;" : "=r"(a), "=r"(b) : "l"(v));
    lo = __uint_as_float(a); hi = __uint_as_float(b);
}

// ---------------------------------------------------------------------------
// init: h[0] = 0, curr_in = x[:,0,:] (transposed), selw[0] = 1, nsel = 0
// ---------------------------------------------------------------------------
__global__ void init_kernel(const float* __restrict__ x, float* __restrict__ selw) {
    int i = blockIdx.x * blockDim.x + threadIdx.x;
    if (i < Hz * Bz) g_hT[0][i] = 0.0f;
    if (i < Fz * Bz) {
        int b = i >> 9;
        int f = i & 511;
        float v = x[(size_t)b * Tz * Fz + f];    // x[b][0][f]
        g_cinT[f * Bz + b] = v;
        selw[(size_t)b * Fz + f] = 1.0f;
    }
    if (i == 0) g_nsel = 0;
}

// ---------------------------------------------------------------------------
// gates GEMM core. 256 threads. warp w = kz(4, K quarter) + 4*bth(2).
// lane = ut(8, bits 2-4) x btq(4, bits 0-1).
// Thread tile: 8 batches (b0..b0+3, 32+b0..32+b0+3) x 1 unit x 3 gates,
// packed as f32x2 pairs. A reads broadcast across the 8 ut-lanes.
// Dynamic smem: As [2][4][16][64] floats (32 KB) + Ws2 [2][4][24][17] ULL
// (duplicated {w,w} pairs, 26 KB), double-buffered with register prefetch.
// ---------------------------------------------------------------------------
#define GATES_SMEM (32768 + 2*4*24*17*8)

template<int KQ, int NC, int LDW>
__device__ __forceinline__ void gemm_gates(
    const float* __restrict__ actT,    // [k][b]
    const float* __restrict__ Wsrc,    // [3*Hz][LDW]
    float* As, ULL* Ws2,
    int j0, int tid, int kz, int ut, int b0,
    ULL* accr, ULL* accz, ULL* accn)
{
    float4 pa[4];
    float4 pw[2];

    auto ldA = [&](int c) {
        #pragma unroll
        for (int i = 0; i < 4; i++) {
            int lin = tid + i * 256;
            int q   = lin >> 8;
            int rem = lin & 255;
            int k   = rem >> 4;
            int b4  = (rem & 15) << 2;
            pa[i] = *(const float4*)(actT + (size_t)(q * KQ + c * 16 + k) * Bz + b4);
        }
        #pragma unroll
        for (int i = 0; i < 2; i++) {
            int lin = tid + i * 256;
            if (lin < 384) {
                int row = lin >> 4;             // 0..23 (g*8 + u)
                int kq4 = lin & 15;
                int q   = kq4 >> 2;
                int qf  = kq4 & 3;
                int g   = row >> 3;
                int uu  = row & 7;
                pw[i] = *(const float4*)(Wsrc + (size_t)(g * Hz + j0 + uu) * LDW
                                         + q * KQ + c * 16 + qf * 4);
            }
        }
    };
    auto stA = [&](int p) {
        #pragma unroll
        for (int i = 0; i < 4; i++) {
            int lin = tid + i * 256;
            int q   = lin >> 8;
            int rem = lin & 255;
            int k   = rem >> 4;
            int b4  = (rem & 15) << 2;
            *(float4*)&As[(((p * 4 + q) * 16) + k) * 64 + b4] = pa[i];
        }
        #pragma unroll
        for (int i = 0; i < 2; i++) {
            int lin = tid + i * 256;
            if (lin < 384) {
                int row = lin >> 4;
                int kq4 = lin & 15;
                int q   = kq4 >> 2;
                int qf  = kq4 & 3;
                ULL* dst = Ws2 + ((size_t)((p * 4 + q) * 24 + row) * 17 + qf * 4);
                float wv[4] = {pw[i].x, pw[i].y, pw[i].z, pw[i].w};
                #pragma unroll
                for (int m = 0; m < 4; m++) dst[m] = dup2(wv[m]);
            }
        }
    };
    auto comp = [&](int p) {
        #pragma unroll
        for (int kk = 0; kk < 16; kk++) {
            const float* arow = As + (((p * 4 + kz) * 16) + kk) * 64;
            ulonglong2 a0 = *(const ulonglong2*)(arow + b0);
            ulonglong2 a1 = *(const ulonglong2*)(arow + 32 + b0);
            const ULL* wb = Ws2 + (size_t)(p * 4 + kz) * 24 * 17 + kk;
            ULL wr = wb[(0 * 8 + ut) * 17];
            ULL wz = wb[(1 * 8 + ut) * 17];
            ULL wn = wb[(2 * 8 + ut) * 17];
            ffma2(accr[0], a0.x, wr); ffma2(accr[1], a0.y, wr);
            ffma2(accr[2], a1.x, wr); ffma2(accr[3], a1.y, wr);
            ffma2(accz[0], a0.x, wz); ffma2(accz[1], a0.y, wz);
            ffma2(accz[2], a1.x, wz); ffma2(accz[3], a1.y, wz);
            ffma2(accn[0], a0.x, wn); ffma2(accn[1], a0.y, wn);
            ffma2(accn[2], a1.x, wn); ffma2(accn[3], a1.y, wn);
        }
    };

    ldA(0);
    stA(0);
    __syncthreads();
    for (int c = 0; c < NC; c++) {
        if (c + 1 < NC) ldA(c + 1);
        comp(c & 1);
        if (c + 1 < NC) stA((c + 1) & 1);
        __syncthreads();
    }
}

// ---------------------------------------------------------------------------
// gates: gi = curr_in @ W_ih^T, gh = h @ W_hh^T, GRU update -> hT[(t+1)&1]
// grid 128 (8 units each) x 256 threads
// ---------------------------------------------------------------------------
__global__ __launch_bounds__(256) void gates_kernel(
    int t,
    const float* __restrict__ Wih, const float* __restrict__ bih,
    const float* __restrict__ Whh, const float* __restrict__ bhh)
{
    extern __shared__ __align__(16) char smem[];
    float* As = (float*)smem;                  // [2][4][16][64]
    ULL*  Ws2 = (ULL*)(smem + 32768);          // [2][4][24][17]
    ULL*  Red = (ULL*)smem;                    // reduction scratch (reuses As)

    const float* __restrict__ hinT = g_hT[t & 1];
    float* __restrict__ houtT = g_hT[(t + 1) & 1];

    const int tid  = threadIdx.x;
    const int w    = tid >> 5;
    const int lane = tid & 31;
    const int kz   = w & 3;
    const int bth  = w >> 2;
    const int ut   = lane >> 2;
    const int btq  = lane & 3;
    const int b0   = bth * 16 + btq * 4;
    const int j0   = blockIdx.x * 8;

    ULL accr[4]  = {0,0,0,0};
    ULL accz[4]  = {0,0,0,0};
    ULL accni[4] = {0,0,0,0};
    ULL accnh[4] = {0,0,0,0};

    // input contribution: K = 512 (KQ = 128, 8 chunks of 64)
    gemm_gates<128, 8, 512>(g_cinT, Wih, As, Ws2, j0, tid, kz, ut, b0, accr, accz, accni);
    // hidden contribution: K = 1024 (KQ = 256, 16 chunks of 64)
    gemm_gates<256, 16, 1024>(hinT, Whh, As, Ws2, j0, tid, kz, ut, b0, accr, accz, accnh);

    // cross-warp K reduction (kz quarters live in different warps)
    __syncthreads();
    if (kz != 0) {
        ULL* dst = Red + (size_t)((bth * 3 + (kz - 1)) * 32 + lane) * 16;
        #pragma unroll
        for (int m = 0; m < 4; m++) {
            dst[m]      = accr[m];
            dst[4 + m]  = accz[m];
            dst[8 + m]  = accni[m];
            dst[12 + m] = accnh[m];
        }
    }
    __syncthreads();
    if (kz == 0) {
        #pragma unroll
        for (int q = 0; q < 3; q++) {
            const ULL* src = Red + (size_t)((bth * 3 + q) * 32 + lane) * 16;
            #pragma unroll
            for (int m = 0; m < 4; m++) {
                fadd2(accr[m],  src[m]);
                fadd2(accz[m],  src[4 + m]);
                fadd2(accni[m], src[8 + m]);
                fadd2(accnh[m], src[12 + m]);
            }
        }

        int j = j0 + ut;
        float br  = bih[j] + bhh[j];
        float bz  = bih[Hz + j] + bhh[Hz + j];
        float bni = bih[2 * Hz + j];
        float bnh = bhh[2 * Hz + j];

        float ar[8], az[8], ani[8], anh[8];
        #pragma unroll
        for (int m = 0; m < 4; m++) {
            unpk(accr[m],  ar[m*2],  ar[m*2+1]);
            unpk(accz[m],  az[m*2],  az[m*2+1]);
            unpk(accni[m], ani[m*2], ani[m*2+1]);
            unpk(accnh[m], anh[m*2], anh[m*2+1]);
        }
        float4 hp0 = *(const float4*)(hinT + (size_t)j * Bz + b0);
        float4 hp1 = *(const float4*)(hinT + (size_t)j * Bz + 32 + b0);
        float hp[8] = {hp0.x, hp0.y, hp0.z, hp0.w, hp1.x, hp1.y, hp1.z, hp1.w};
        float res[8];
        #pragma unroll
        for (int i = 0; i < 8; i++) {
            float r = sigmf(ar[i] + br);
            float z = sigmf(az[i] + bz);
            float n = tanhf(ani[i] + bni + r * (anh[i] + bnh));
            res[i] = (1.0f - z) * n + z * hp[i];
        }
        *(float4*)&houtT[(size_t)j * Bz + b0]      = make_float4(res[0], res[1], res[2], res[3]);
        *(float4*)&houtT[(size_t)j * Bz + 32 + b0] = make_float4(res[4], res[5], res[6], res[7]);
    }
}

// ---------------------------------------------------------------------------
// houts: 1024 virtual cols (512 out + 512 sel) = h @ [W_out; W_sel]^T + bias.
// Sel-column threads fuse next step's Bernoulli mask.
// grid 128 (8 cols each) x 256 threads: warp = kz(4) x bth(2),
// lane = ct(8) x btq(4). Static smem (fits 48 KB).
// ---------------------------------------------------------------------------
__global__ __launch_bounds__(256) void houts_kernel(
    int t,
    const float* __restrict__ Wout, const float* __restrict__ bout,
    const float* __restrict__ Wsel, const float* __restrict__ bsel,
    const float* __restrict__ x, const float* __restrict__ u,
    float* __restrict__ out, float* __restrict__ selw)
{
    __shared__ __align__(16) float As[2][4][16][64];   // 32 KB
    __shared__ ULL Ws2[2][4][8][17];                   // 8.5 KB
    __shared__ ULL Red[2][3][32][4];                   // 6 KB

    const float* __restrict__ hT = g_hT[(t + 1) & 1];

    const int tid  = threadIdx.x;
    const int w    = tid >> 5;
    const int lane = tid & 31;
    const int kz   = w & 3;
    const int bth  = w >> 2;
    const int ct   = lane >> 2;
    const int btq  = lane & 3;
    const int b0   = bth * 16 + btq * 4;
    const int c0   = blockIdx.x * 8;

    // W staging coords (tid < 128): 8 rows x 16 float4 per chunk
    const int srow = tid >> 4;
    const int skq4 = tid & 15;
    const int sq   = skq4 >> 2;
    const int sqf  = skq4 & 3;
    const int scc  = c0 + srow;
    const float* __restrict__ wrow = (scc < Oz) ? (Wout + (size_t)scc * Hz)
                                                : (Wsel + (size_t)(scc - Oz) * Hz);

    ULL acc[4] = {0,0,0,0};
    float4 pa[4];
    float4 pw;

    auto ldA = [&](int c) {
        #pragma unroll
        for (int i = 0; i < 4; i++) {
            int lin = tid + i * 256;
            int q   = lin >> 8;
            int rem = lin & 255;
            int k   = rem >> 4;
            int b4  = (rem & 15) << 2;
            pa[i] = *(const float4*)(hT + (size_t)(q * 256 + c * 16 + k) * Bz + b4);
        }
        if (tid < 128)
            pw = *(const float4*)(wrow + sq * 256 + c * 16 + sqf * 4);
    };
    auto stA = [&](int p) {
        #pragma unroll
        for (int i = 0; i < 4; i++) {
            int lin = tid + i * 256;
            int q   = lin >> 8;
            int rem = lin & 255;
            int k   = rem >> 4;
            int b4  = (rem & 15) << 2;
            *(float4*)&As[p][q][k][b4] = pa[i];
        }
        if (tid < 128) {
            float wv[4] = {pw.x, pw.y, pw.z, pw.w};
            #pragma unroll
            for (int m = 0; m < 4; m++)
                Ws2[p][sq][srow][sqf * 4 + m] = dup2(wv[m]);
        }
    };
    auto comp = [&](int p) {
        #pragma unroll
        for (int kk = 0; kk < 16; kk++) {
            const float* arow = &As[p][kz][kk][0];
            ulonglong2 a0 = *(const ulonglong2*)(arow + b0);
            ulonglong2 a1 = *(const ulonglong2*)(arow + 32 + b0);
            ULL wc = Ws2[p][kz][ct][kk];
            ffma2(acc[0], a0.x, wc); ffma2(acc[1], a0.y, wc);
            ffma2(acc[2], a1.x, wc); ffma2(acc[3], a1.y, wc);
        }
    };

    ldA(0);
    stA(0);
    __syncthreads();
    for (int c = 0; c < 16; c++) {
        if (c + 1 < 16) ldA(c + 1);
        comp(c & 1);
        if (c + 1 < 16) stA((c + 1) & 1);
        __syncthreads();
    }

    // cross-warp K reduction
    if (kz != 0) {
        #pragma unroll
        for (int m = 0; m < 4; m++) Red[bth][kz - 1][lane][m] = acc[m];
    }
    __syncthreads();

    int cnt = 0;
    if (kz == 0) {
        #pragma unroll
        for (int q = 0; q < 3; q++)
            #pragma unroll
            for (int m = 0; m < 4; m++) fadd2(acc[m], Red[bth][q][lane][m]);

        float av[8];
        #pragma unroll
        for (int m = 0; m < 4; m++) unpk(acc[m], av[m*2], av[m*2+1]);

        int c = c0 + ct;
        if (c < Oz) {
            float bb = bout[c];
            #pragma unroll
            for (int i = 0; i < 8; i++) {
                int b = (i < 4) ? (b0 + i) : (32 + b0 + i - 4);
                out[(size_t)t * Bz * Oz + (size_t)b * Oz + c] = av[i] + bb;
            }
        } else if (t < Tz - 1) {
            int f = c - Oz;
            float bb = bsel[f];
            float cin[8];
            #pragma unroll
            for (int i = 0; i < 8; i++) {
                int b = (i < 4) ? (b0 + i) : (32 + b0 + i - 4);
                float lg = av[i] + bb;
                float sg = sigmf(lg);
                float uu = u[((size_t)(t + 1) * Bz + b) * Fz + f];
                float wv = (sg > uu) ? 1.0f : 0.0f;
                selw[((size_t)(t + 1) * Bz + b) * Fz + f] = wv;
                cnt += (int)wv;
                cin[i] = wv * x[((size_t)b * Tz + t + 1) * Fz + f];
            }
            *(float4*)&g_cinT[f * Bz + b0]      = make_float4(cin[0], cin[1], cin[2], cin[3]);
            *(float4*)&g_cinT[f * Bz + 32 + b0] = make_float4(cin[4], cin[5], cin[6], cin[7]);
        }
    }
    #pragma unroll
    for (int o = 16; o; o >>= 1) cnt += __shfl_down_sync(0xffffffffu, cnt, o);
    if ((tid & 31) == 0 && cnt) atomicAdd(&g_nsel, cnt);
}

// ---------------------------------------------------------------------------
__global__ void finalize_kernel(float* __restrict__ out) {
    out[(size_t)Tz * Bz * Oz] = (float)g_nsel;
}

// ---------------------------------------------------------------------------
extern "C" void kernel_launch(void* const* d_in, const int* in_sizes, int n_in,
                              void* d_out, int out_size) {
    const float* x    = (const float*)d_in[0];
    const float* u    = (const float*)d_in[1];
    const float* Wih  = (const float*)d_in[2];
    const float* bih  = (const float*)d_in[3];
    const float* Whh  = (const float*)d_in[4];
    const float* bhh  = (const float*)d_in[5];
    const float* Wout = (const float*)d_in[6];
    const float* bout = (const float*)d_in[7];
    const float* Wsel = (const float*)d_in[8];
    const float* bsel = (const float*)d_in[9];

    float* out  = (float*)d_out;
    float* selw = out + (size_t)Tz * Bz * Oz + 1;

    cudaFuncSetAttribute(gates_kernel, cudaFuncAttributeMaxDynamicSharedMemorySize,
                         GATES_SMEM);

    init_kernel<<<(Hz * Bz + 255) / 256, 256>>>(x, selw);
    for (int t = 0; t < Tz; t++) {
        gates_kernel<<<128, 256, GATES_SMEM>>>(t, Wih, bih, Whh, bhh);
        houts_kernel<<<128, 256>>>(t, Wout, bout, Wsel, bsel, x, u, out, selw);
    }
    finalize_kernel<<<1, 1>>>(out);
}

// round 9
// speedup vs baseline: 1.1090x; 1.1090x over previous
#include <cuda_runtime.h>
#include <math.h>

#define Bz 64
#define Tz 256
#define Fz 512
#define Hz 1024
#define Oz 512

// Persistent device state (transposed layouts: [feature][batch])
__device__ __align__(16) float g_hT[2][Hz * Bz];   // hidden state ping-pong, [j][b]
__device__ __align__(16) float g_cinT[Fz * Bz];    // masked input, [f][b]
__device__ int g_nsel;

__device__ __forceinline__ float sigmf(float v) { return 1.0f / (1.0f + expf(-v)); }

__device__ __forceinline__ unsigned cvt_tf32(float f) {
    unsigned r; asm("cvt.rna.tf32.f32 %0, %1;" : "=r"(r) : "f"(f)); return r;
}
// 3xTF32 split: a = hi + lo with both tf32-representable; hi*hi, hi*lo, lo*hi
// are exact products -> fp32-accuracy GEMM on tensor cores.
__device__ __forceinline__ void split_tf32(float f, unsigned& hi, unsigned& lo) {
    hi = cvt_tf32(f);
    lo = cvt_tf32(f - __uint_as_float(hi));
}

// D += A(16x8) * B(8x8), tf32 operands, fp32 accum
__device__ __forceinline__ void mma_tf32(float* d, const unsigned* a, const unsigned* b) {
    asm volatile(
        "mma.sync.aligned.m16n8k8.row.col.f32.tf32.tf32.f32 "
        "{%0,%1,%2,%3}, {%4,%5,%6,%7}, {%8,%9}, {%0,%1,%2,%3};"
        : "+f"(d[0]), "+f"(d[1]), "+f"(d[2]), "+f"(d[3])
        : "r"(a[0]), "r"(a[1]), "r"(a[2]), "r"(a[3]), "r"(b[0]), "r"(b[1]));
}

// ---------------------------------------------------------------------------
// init: h[0] = 0, curr_in = x[:,0,:] (transposed), selw[0] = 1, nsel = 0
// ---------------------------------------------------------------------------
__global__ void init_kernel(const float* __restrict__ x, float* __restrict__ selw) {
    int i = blockIdx.x * blockDim.x + threadIdx.x;
    if (i < Hz * Bz) g_hT[0][i] = 0.0f;
    if (i < Fz * Bz) {
        int b = i >> 9;
        int f = i & 511;
        float v = x[(size_t)b * Tz * Fz + f];
        g_cinT[f * Bz + b] = v;
        selw[(size_t)b * Fz + f] = 1.0f;
    }
    if (i == 0) g_nsel = 0;
}

// ---------------------------------------------------------------------------
// gates: C[64 b x 24 v], v = jl*3 + gate, K = 512 (cin) + 1024 (h).
// 8 warps K-split (8 k each per 64-k chunk); 3xTF32 (hi/lo) operands.
// Dynamic smem: AsHi/AsLo [2][64*68] + WsHi/WsLo [2][24*68] = 95.7 KB,
// reused as Cred[8][1600] fp32 (51.2 KB) in the epilogue.
// ---------------------------------------------------------------------------
#define GATES_SMEM ((2*4352*2 + 2*1632*2) * 4)

__global__ __launch_bounds__(256) void gates_kernel(
    int t,
    const float* __restrict__ Wih, const float* __restrict__ bih,
    const float* __restrict__ Whh, const float* __restrict__ bhh)
{
    extern __shared__ unsigned smem_u[];
    unsigned* AsHi = smem_u;                      // [2][4352]
    unsigned* AsLo = smem_u + 2 * 4352;           // [2][4352]
    unsigned* WsHi = smem_u + 4 * 4352;           // [2][1632]
    unsigned* WsLo = smem_u + 4 * 4352 + 2 * 1632;
    float* Cred = (float*)smem_u;                 // epilogue reuse [8][1600]

    const float* __restrict__ hinT = g_hT[t & 1];
    float* __restrict__ houtT = g_hT[(t + 1) & 1];

    const int tid  = threadIdx.x;
    const int w    = tid >> 5;
    const int lane = tid & 31;
    const int g    = lane >> 2;
    const int tig  = lane & 3;
    const int j0   = blockIdx.x * 8;

    float accI[48] = {};    // chunks 0-7  (K-input)
    float accH[48] = {};    // chunks 8-23 (K-hidden)

    float4 pa[4];
    float4 pw[2];

    auto ldA = [&](int c) {
        const float* src; int koff;
        if (c < 8) { src = g_cinT; koff = c * 64; }
        else       { src = hinT;   koff = (c - 8) * 64; }
        #pragma unroll
        for (int i = 0; i < 4; i++) {
            int idx = tid + i * 256;
            int k = idx >> 4, b4 = (idx & 15) << 2;
            pa[i] = *(const float4*)(src + (size_t)(koff + k) * Bz + b4);
        }
        #pragma unroll
        for (int i = 0; i < 2; i++) {
            int lin = tid + i * 256;
            if (lin < 384) {
                int v = lin >> 4, kq4 = (lin & 15) << 2;
                int gg = v % 3, jl = v / 3;
                const float* wptr = (c < 8)
                    ? (Wih + (size_t)(gg * Hz + j0 + jl) * 512 + koff + kq4)
                    : (Whh + (size_t)(gg * Hz + j0 + jl) * 1024 + koff + kq4);
                pw[i] = *(const float4*)wptr;
            }
        }
    };
    auto stA = [&](int p) {
        unsigned* AH = AsHi + p * 4352;
        unsigned* AL = AsLo + p * 4352;
        unsigned* WH = WsHi + p * 1632;
        unsigned* WL = WsLo + p * 1632;
        #pragma unroll
        for (int i = 0; i < 4; i++) {
            int idx = tid + i * 256;
            int k = idx >> 4, b4 = (idx & 15) << 2;
            unsigned hi[4], lo[4];
            split_tf32(pa[i].x, hi[0], lo[0]); split_tf32(pa[i].y, hi[1], lo[1]);
            split_tf32(pa[i].z, hi[2], lo[2]); split_tf32(pa[i].w, hi[3], lo[3]);
            unsigned* dh = AH + k * 68 + b4;
            unsigned* dl = AL + k * 68 + b4;
            #pragma unroll
            for (int m = 0; m < 4; m++) { dh[m] = hi[m]; dl[m] = lo[m]; }
        }
        #pragma unroll
        for (int i = 0; i < 2; i++) {
            int lin = tid + i * 256;
            if (lin < 384) {
                int v = lin >> 4, kq4 = (lin & 15) << 2;
                float wv[4] = {pw[i].x, pw[i].y, pw[i].z, pw[i].w};
                unsigned* dh = WH + v * 68 + kq4;
                unsigned* dl = WL + v * 68 + kq4;
                #pragma unroll
                for (int m = 0; m < 4; m++) {
                    unsigned hi, lo; split_tf32(wv[m], hi, lo);
                    dh[m] = hi; dl[m] = lo;
                }
            }
        }
    };
    auto comp = [&](int p, float* acc) {
        const unsigned* AH = AsHi + p * 4352;
        const unsigned* AL = AsLo + p * 4352;
        const unsigned* WH = WsHi + p * 1632;
        const unsigned* WL = WsLo + p * 1632;
        const int k0 = w * 8;
        unsigned bfh[3][2], bfl[3][2];
        #pragma unroll
        for (int nf = 0; nf < 3; nf++) {
            int base = (nf * 8 + g) * 68 + k0 + tig;
            bfh[nf][0] = WH[base];     bfh[nf][1] = WH[base + 4];
            bfl[nf][0] = WL[base];     bfl[nf][1] = WL[base + 4];
        }
        #pragma unroll
        for (int mf = 0; mf < 4; mf++) {
            unsigned afh[4], afl[4];
            int i0 = (k0 + tig) * 68 + mf * 16 + g;
            int i1 = (k0 + tig + 4) * 68 + mf * 16 + g;
            afh[0] = AH[i0]; afh[1] = AH[i0 + 8]; afh[2] = AH[i1]; afh[3] = AH[i1 + 8];
            afl[0] = AL[i0]; afl[1] = AL[i0 + 8]; afl[2] = AL[i1]; afl[3] = AL[i1 + 8];
            #pragma unroll
            for (int nf = 0; nf < 3; nf++) {
                float* d = acc + (mf * 3 + nf) * 4;
                mma_tf32(d, afh, bfh[nf]);
                mma_tf32(d, afh, bfl[nf]);
                mma_tf32(d, afl, bfh[nf]);
            }
        }
    };

    ldA(0); stA(0); __syncthreads();
    for (int c = 0; c < 24; c++) {
        if (c + 1 < 24) ldA(c + 1);
        comp(c & 1, (c < 8) ? accI : accH);
        if (c + 1 < 24) stA((c + 1) & 1);
        __syncthreads();
    }

    // ---- epilogue: 8-way cross-warp reduction (two sets), then GRU ----
    float sI[2][3], sH[2][3];

    #pragma unroll
    for (int mf = 0; mf < 4; mf++)
        #pragma unroll
        for (int nf = 0; nf < 3; nf++) {
            const float* d = accI + (mf * 3 + nf) * 4;
            int mb = mf * 16, nb = nf * 8;
            Cred[w * 1600 + (mb + g) * 25 + nb + 2 * tig]         = d[0];
            Cred[w * 1600 + (mb + g) * 25 + nb + 2 * tig + 1]     = d[1];
            Cred[w * 1600 + (mb + g + 8) * 25 + nb + 2 * tig]     = d[2];
            Cred[w * 1600 + (mb + g + 8) * 25 + nb + 2 * tig + 1] = d[3];
        }
    __syncthreads();
    #pragma unroll
    for (int e = 0; e < 2; e++) {
        int pid = tid + e * 256;
        int b = pid & 63, jl = pid >> 6;
        #pragma unroll
        for (int g3 = 0; g3 < 3; g3++) {
            float s = 0.f;
            #pragma unroll
            for (int w8 = 0; w8 < 8; w8++) s += Cred[w8 * 1600 + b * 25 + jl * 3 + g3];
            sI[e][g3] = s;
        }
    }
    __syncthreads();
    #pragma unroll
    for (int mf = 0; mf < 4; mf++)
        #pragma unroll
        for (int nf = 0; nf < 3; nf++) {
            const float* d = accH + (mf * 3 + nf) * 4;
            int mb = mf * 16, nb = nf * 8;
            Cred[w * 1600 + (mb + g) * 25 + nb + 2 * tig]         = d[0];
            Cred[w * 1600 + (mb + g) * 25 + nb + 2 * tig + 1]     = d[1];
            Cred[w * 1600 + (mb + g + 8) * 25 + nb + 2 * tig]     = d[2];
            Cred[w * 1600 + (mb + g + 8) * 25 + nb + 2 * tig + 1] = d[3];
        }
    __syncthreads();
    #pragma unroll
    for (int e = 0; e < 2; e++) {
        int pid = tid + e * 256;
        int b = pid & 63, jl = pid >> 6;
        #pragma unroll
        for (int g3 = 0; g3 < 3; g3++) {
            float s = 0.f;
            #pragma unroll
            for (int w8 = 0; w8 < 8; w8++) s += Cred[w8 * 1600 + b * 25 + jl * 3 + g3];
            sH[e][g3] = s;
        }
    }

    #pragma unroll
    for (int e = 0; e < 2; e++) {
        int pid = tid + e * 256;
        int b = pid & 63, jl = pid >> 6;
        int j = j0 + jl;
        float br  = bih[j] + bhh[j];
        float bz  = bih[Hz + j] + bhh[Hz + j];
        float bni = bih[2 * Hz + j];
        float bnh = bhh[2 * Hz + j];
        float r = sigmf(sI[e][0] + sH[e][0] + br);
        float z = sigmf(sI[e][1] + sH[e][1] + bz);
        float n = tanhf(sI[e][2] + bni + r * (sH[e][2] + bnh));
        float hp = hinT[(size_t)j * Bz + b];
        houtT[(size_t)j * Bz + b] = (1.0f - z) * n + z * hp;
    }
}

// ---------------------------------------------------------------------------
// houts: C[64 b x 8 cols] over 1024 virtual cols (512 out + 512 sel),
// K = 1024, 3xTF32. Sel blocks fuse the Bernoulli mask epilogue.
// Dynamic smem: AsHi/Lo + WsHi/Lo = 78.3 KB; Cred[8][576] reuses it.
// ---------------------------------------------------------------------------
#define HOUTS_SMEM ((2*4352*2 + 2*544*2) * 4)

__global__ __launch_bounds__(256) void houts_kernel(
    int t,
    const float* __restrict__ Wout, const float* __restrict__ bout,
    const float* __restrict__ Wsel, const float* __restrict__ bsel,
    const float* __restrict__ x, const float* __restrict__ u,
    float* __restrict__ out, float* __restrict__ selw)
{
    extern __shared__ unsigned smem_u[];
    unsigned* AsHi = smem_u;                      // [2][4352]
    unsigned* AsLo = smem_u + 2 * 4352;
    unsigned* WsHi = smem_u + 4 * 4352;           // [2][544]
    unsigned* WsLo = smem_u + 4 * 4352 + 2 * 544;
    float* Cred = (float*)smem_u;                 // [8][576]

    const float* __restrict__ hT = g_hT[(t + 1) & 1];

    const int tid  = threadIdx.x;
    const int w    = tid >> 5;
    const int lane = tid & 31;
    const int g    = lane >> 2;
    const int tig  = lane & 3;
    const int c0   = blockIdx.x * 8;

    float acc[16] = {};
    float4 pa[4];
    float4 pw;

    auto ldA = [&](int c) {
        int koff = c * 64;
        #pragma unroll
        for (int i = 0; i < 4; i++) {
            int idx = tid + i * 256;
            int k = idx >> 4, b4 = (idx & 15) << 2;
            pa[i] = *(const float4*)(hT + (size_t)(koff + k) * Bz + b4);
        }
        if (tid < 128) {
            int v = tid >> 4, kq4 = (tid & 15) << 2;
            int cc = c0 + v;
            const float* wptr = (cc < Oz) ? (Wout + (size_t)cc * Hz)
                                          : (Wsel + (size_t)(cc - Oz) * Hz);
            pw = *(const float4*)(wptr + koff + kq4);
        }
    };
    auto stA = [&](int p) {
        unsigned* AH = AsHi + p * 4352;
        unsigned* AL = AsLo + p * 4352;
        unsigned* WH = WsHi + p * 544;
        unsigned* WL = WsLo + p * 544;
        #pragma unroll
        for (int i = 0; i < 4; i++) {
            int idx = tid + i * 256;
            int k = idx >> 4, b4 = (idx & 15) << 2;
            unsigned hi[4], lo[4];
            split_tf32(pa[i].x, hi[0], lo[0]); split_tf32(pa[i].y, hi[1], lo[1]);
            split_tf32(pa[i].z, hi[2], lo[2]); split_tf32(pa[i].w, hi[3], lo[3]);
            unsigned* dh = AH + k * 68 + b4;
            unsigned* dl = AL + k * 68 + b4;
            #pragma unroll
            for (int m = 0; m < 4; m++) { dh[m] = hi[m]; dl[m] = lo[m]; }
        }
        if (tid < 128) {
            int v = tid >> 4, kq4 = (tid & 15) << 2;
            float wv[4] = {pw.x, pw.y, pw.z, pw.w};
            unsigned* dh = WH + v * 68 + kq4;
            unsigned* dl = WL + v * 68 + kq4;
            #pragma unroll
            for (int m = 0; m < 4; m++) {
                unsigned hi, lo; split_tf32(wv[m], hi, lo);
                dh[m] = hi; dl[m] = lo;
            }
        }
    };
    auto comp = [&](int p) {
        const unsigned* AH = AsHi + p * 4352;
        const unsigned* AL = AsLo + p * 4352;
        const unsigned* WH = WsHi + p * 544;
        const unsigned* WL = WsLo + p * 544;
        const int k0 = w * 8;
        unsigned bfh[2], bfl[2];
        int base = g * 68 + k0 + tig;
        bfh[0] = WH[base]; bfh[1] = WH[base + 4];
        bfl[0] = WL[base]; bfl[1] = WL[base + 4];
        #pragma unroll
        for (int mf = 0; mf < 4; mf++) {
            unsigned afh[4], afl[4];
            int i0 = (k0 + tig) * 68 + mf * 16 + g;
            int i1 = (k0 + tig + 4) * 68 + mf * 16 + g;
            afh[0] = AH[i0]; afh[1] = AH[i0 + 8]; afh[2] = AH[i1]; afh[3] = AH[i1 + 8];
            afl[0] = AL[i0]; afl[1] = AL[i0 + 8]; afl[2] = AL[i1]; afl[3] = AL[i1 + 8];
            float* d = acc + mf * 4;
            mma_tf32(d, afh, bfh);
            mma_tf32(d, afh, bfl);
            mma_tf32(d, afl, bfh);
        }
    };

    ldA(0); stA(0); __syncthreads();
    for (int c = 0; c < 16; c++) {
        if (c + 1 < 16) ldA(c + 1);
        comp(c & 1);
        if (c + 1 < 16) stA((c + 1) & 1);
        __syncthreads();
    }

    // ---- epilogue: 8-way reduction, then out-write or fused mask ----
    #pragma unroll
    for (int mf = 0; mf < 4; mf++) {
        const float* d = acc + mf * 4;
        int mb = mf * 16;
        Cred[w * 576 + (mb + g) * 9 + 2 * tig]         = d[0];
        Cred[w * 576 + (mb + g) * 9 + 2 * tig + 1]     = d[1];
        Cred[w * 576 + (mb + g + 8) * 9 + 2 * tig]     = d[2];
        Cred[w * 576 + (mb + g + 8) * 9 + 2 * tig + 1] = d[3];
    }
    __syncthreads();

    int cnt = 0;
    #pragma unroll
    for (int e = 0; e < 2; e++) {
        int pid = tid + e * 256;
        int b = pid & 63, cl = pid >> 6;
        float s = 0.f;
        #pragma unroll
        for (int w8 = 0; w8 < 8; w8++) s += Cred[w8 * 576 + b * 9 + cl];
        int c = c0 + cl;
        if (c < Oz) {
            out[(size_t)t * Bz * Oz + (size_t)b * Oz + c] = s + bout[c];
        } else if (t < Tz - 1) {
            int f = c - Oz;
            float lg = s + bsel[f];
            float sg = sigmf(lg);
            float uu = u[((size_t)(t + 1) * Bz + b) * Fz + f];
            float wv = (sg > uu) ? 1.0f : 0.0f;
            selw[((size_t)(t + 1) * Bz + b) * Fz + f] = wv;
            cnt += (int)wv;
            g_cinT[f * Bz + b] = wv * x[((size_t)b * Tz + t + 1) * Fz + f];
        }
    }
    #pragma unroll
    for (int o = 16; o; o >>= 1) cnt += __shfl_down_sync(0xffffffffu, cnt, o);
    if ((tid & 31) == 0 && cnt) atomicAdd(&g_nsel, cnt);
}

// ---------------------------------------------------------------------------
__global__ void finalize_kernel(float* __restrict__ out) {
    out[(size_t)Tz * Bz * Oz] = (float)g_nsel;
}

// ---------------------------------------------------------------------------
extern "C" void kernel_launch(void* const* d_in, const int* in_sizes, int n_in,
                              void* d_out, int out_size) {
    const float* x    = (const float*)d_in[0];
    const float* u    = (const float*)d_in[1];
    const float* Wih  = (const float*)d_in[2];
    const float* bih  = (const float*)d_in[3];
    const float* Whh  = (const float*)d_in[4];
    const float* bhh  = (const float*)d_in[5];
    const float* Wout = (const float*)d_in[6];
    const float* bout = (const float*)d_in[7];
    const float* Wsel = (const float*)d_in[8];
    const float* bsel = (const float*)d_in[9];

    float* out  = (float*)d_out;
    float* selw = out + (size_t)Tz * Bz * Oz + 1;

    cudaFuncSetAttribute(gates_kernel, cudaFuncAttributeMaxDynamicSharedMemorySize, GATES_SMEM);
    cudaFuncSetAttribute(houts_kernel, cudaFuncAttributeMaxDynamicSharedMemorySize, HOUTS_SMEM);

    init_kernel<<<(Hz * Bz + 255) / 256, 256>>>(x, selw);
    for (int t = 0; t < Tz; t++) {
        gates_kernel<<<128, 256, GATES_SMEM>>>(t, Wih, bih, Whh, bhh);
        houts_kernel<<<128, 256, HOUTS_SMEM>>>(t, Wout, bout, Wsel, bsel, x, u, out, selw);
    }
    finalize_kernel<<<1, 1>>>(out);
}

// round 11
// speedup vs baseline: 2.0100x; 1.8124x over previous
#include <cuda_runtime.h>
#include <math.h>

#define Bz 64
#define Tz 256
#define Fz 512
#define Hz 1024
#define Oz 512

// Persistent device state (transposed layouts: [feature][batch])
__device__ __align__(16) float g_hT[2][Hz * Bz];   // hidden state ping-pong, [j][b]
__device__ __align__(16) float g_cinT[Fz * Bz];    // masked input, [f][b]
__device__ int g_nsel;

__device__ __forceinline__ float sigmf(float v) { return 1.0f / (1.0f + expf(-v)); }

// Truncation split for 3xTF32: hi = x with low 13 mantissa bits cleared
// (exactly tf32-representable); lo = x - hi (exact). hi*hi + hi*lo + lo*hi
// on tensor cores gives fp32-accuracy GEMM.
__device__ __forceinline__ void split_mask(float f, unsigned& hi, unsigned& lo) {
    unsigned x = __float_as_uint(f);
    hi = x & 0xFFFFE000u;
    lo = __float_as_uint(f - __uint_as_float(hi));
}

// D += A(16x8) * B(8x8), tf32 operands, fp32 accum
__device__ __forceinline__ void mma_tf32(float* d, const unsigned* a, const unsigned* b) {
    asm volatile(
        "mma.sync.aligned.m16n8k8.row.col.f32.tf32.tf32.f32 "
        "{%0,%1,%2,%3}, {%4,%5,%6,%7}, {%8,%9}, {%0,%1,%2,%3};"
        : "+f"(d[0]), "+f"(d[1]), "+f"(d[2]), "+f"(d[3])
        : "r"(a[0]), "r"(a[1]), "r"(a[2]), "r"(a[3]), "r"(b[0]), "r"(b[1]));
}

// ---------------------------------------------------------------------------
// init: h[0] = 0, curr_in = x[:,0,:] (transposed), selw[0] = 1, nsel = 0
// ---------------------------------------------------------------------------
__global__ void init_kernel(const float* __restrict__ x, float* __restrict__ selw) {
    int i = blockIdx.x * blockDim.x + threadIdx.x;
    if (i < Hz * Bz) g_hT[0][i] = 0.0f;
    if (i < Fz * Bz) {
        int b = i >> 9;
        int f = i & 511;
        float v = x[(size_t)b * Tz * Fz + f];
        g_cinT[f * Bz + b] = v;
        selw[(size_t)b * Fz + f] = 1.0f;
    }
    if (i == 0) g_nsel = 0;
}

// ---------------------------------------------------------------------------
// gates: C[64 b x 24 v], gate-major v = gate*8 + jl, K = 512 (cin) + 1024 (h).
// 8 warps K-split: k8-step s = c*8 + w; c<8 is the input part (so accNI /
// accNH split the n-gate exactly). NO smem staging: fragments loaded
// global->register (each element consumed by exactly one lane), split in
// registers. Smem used only for the epilogue cross-warp reduction.
// ---------------------------------------------------------------------------
#define GATES_SMEM (8 * 64 * 25 * 4)     // 51200 B

__global__ __launch_bounds__(256) void gates_kernel(
    int t,
    const float* __restrict__ Wih, const float* __restrict__ bih,
    const float* __restrict__ Whh, const float* __restrict__ bhh)
{
    extern __shared__ float Cred[];      // [8][64][25] pass1 / [8][64][9] pass2

    const float* __restrict__ hinT = g_hT[t & 1];
    float* __restrict__ houtT = g_hT[(t + 1) & 1];

    const int tid  = threadIdx.x;
    const int w    = tid >> 5;
    const int lane = tid & 31;
    const int g    = lane >> 2;
    const int tig  = lane & 3;
    const int j0   = blockIdx.x * 8;

    float accRZ[2][4][4] = {};   // [nf=r,z][mf][4]
    float accNI[4][4] = {};      // n-gate, input K-part (c<8)
    float accNH[4][4] = {};      // n-gate, hidden K-part

    // lane-private W row pointers (B-fragment row v = nf*8 + g)
    const float* wih_row[3];
    const float* whh_row[3];
    #pragma unroll
    for (int nf = 0; nf < 3; nf++) {
        wih_row[nf] = Wih + (size_t)(nf * Hz + j0 + g) * Fz;
        whh_row[nf] = Whh + (size_t)(nf * Hz + j0 + g) * Hz;
    }

    float araw[4][4];
    float wraw[3][2];

    auto loadRaw = [&](int c) {
        int s = c * 8 + w;
        const float* A;
        int kg;
        if (s < 64) { A = g_cinT; kg = s * 8; }
        else        { A = hinT;   kg = s * 8 - 512; }
        const float* r0 = A + (size_t)(kg + tig) * Bz;
        const float* r1 = A + (size_t)(kg + tig + 4) * Bz;
        #pragma unroll
        for (int mf = 0; mf < 4; mf++) {
            araw[mf][0] = r0[mf * 16 + g];
            araw[mf][1] = r0[mf * 16 + 8 + g];
            araw[mf][2] = r1[mf * 16 + g];
            araw[mf][3] = r1[mf * 16 + 8 + g];
        }
        #pragma unroll
        for (int nf = 0; nf < 3; nf++) {
            const float* wr = (s < 64) ? (wih_row[nf] + kg) : (whh_row[nf] + kg);
            wraw[nf][0] = wr[tig];
            wraw[nf][1] = wr[tig + 4];
        }
    };

    auto chunk_body = [&](int c, float (&accN)[4][4]) {
        unsigned afh[4][4], afl[4][4], bfh[3][2], bfl[3][2];
        #pragma unroll
        for (int mf = 0; mf < 4; mf++)
            #pragma unroll
            for (int i = 0; i < 4; i++)
                split_mask(araw[mf][i], afh[mf][i], afl[mf][i]);
        #pragma unroll
        for (int nf = 0; nf < 3; nf++)
            #pragma unroll
            for (int i = 0; i < 2; i++)
                split_mask(wraw[nf][i], bfh[nf][i], bfl[nf][i]);
        if (c + 1 < 24) loadRaw(c + 1);
        #pragma unroll
        for (int mf = 0; mf < 4; mf++) {
            mma_tf32(accRZ[0][mf], afh[mf], bfh[0]);
            mma_tf32(accRZ[0][mf], afh[mf], bfl[0]);
            mma_tf32(accRZ[0][mf], afl[mf], bfh[0]);
            mma_tf32(accRZ[1][mf], afh[mf], bfh[1]);
            mma_tf32(accRZ[1][mf], afh[mf], bfl[1]);
            mma_tf32(accRZ[1][mf], afl[mf], bfh[1]);
            mma_tf32(accN[mf],     afh[mf], bfh[2]);
            mma_tf32(accN[mf],     afh[mf], bfl[2]);
            mma_tf32(accN[mf],     afl[mf], bfh[2]);
        }
    };

    loadRaw(0);
    for (int c = 0; c < 8; c++)  chunk_body(c, accNI);
    for (int c = 8; c < 24; c++) chunk_body(c, accNH);

    // ---- epilogue pass 1: r (cols 0-7), z (8-15), nI (16-23) ----
    #pragma unroll
    for (int mf = 0; mf < 4; mf++) {
        int rowb = w * 1600 + (mf * 16 + g) * 25;
        #pragma unroll
        for (int nf = 0; nf < 2; nf++) {
            const float* d = accRZ[nf][mf];
            int base = rowb + nf * 8 + 2 * tig;
            Cred[base] = d[0];       Cred[base + 1] = d[1];
            Cred[base + 200] = d[2]; Cred[base + 201] = d[3];
        }
        const float* d = accNI[mf];
        int base = rowb + 16 + 2 * tig;
        Cred[base] = d[0];       Cred[base + 1] = d[1];
        Cred[base + 200] = d[2]; Cred[base + 201] = d[3];
    }
    __syncthreads();

    float sR[2], sZ[2], sNI[2], sNH[2];
    #pragma unroll
    for (int e = 0; e < 2; e++) {
        int pid = tid + e * 256;
        int b = pid & 63, jl = pid >> 6;
        sR[e] = 0.f; sZ[e] = 0.f; sNI[e] = 0.f;
        #pragma unroll
        for (int w8 = 0; w8 < 8; w8++) {
            const float* p = Cred + w8 * 1600 + b * 25;
            sR[e]  += p[jl];
            sZ[e]  += p[8 + jl];
            sNI[e] += p[16 + jl];
        }
    }
    __syncthreads();

    // ---- epilogue pass 2: nH (8 cols, pad 9) ----
    #pragma unroll
    for (int mf = 0; mf < 4; mf++) {
        const float* d = accNH[mf];
        int base = w * 576 + (mf * 16 + g) * 9 + 2 * tig;
        Cred[base] = d[0];      Cred[base + 1] = d[1];
        Cred[base + 72] = d[2]; Cred[base + 73] = d[3];
    }
    __syncthreads();
    #pragma unroll
    for (int e = 0; e < 2; e++) {
        int pid = tid + e * 256;
        int b = pid & 63, jl = pid >> 6;
        float s = 0.f;
        #pragma unroll
        for (int w8 = 0; w8 < 8; w8++) s += Cred[w8 * 576 + b * 9 + jl];
        sNH[e] = s;
    }

    // ---- GRU update ----
    #pragma unroll
    for (int e = 0; e < 2; e++) {
        int pid = tid + e * 256;
        int b = pid & 63, jl = pid >> 6;
        int j = j0 + jl;
        float br  = bih[j] + bhh[j];
        float bz  = bih[Hz + j] + bhh[Hz + j];
        float bni = bih[2 * Hz + j];
        float bnh = bhh[2 * Hz + j];
        float r = sigmf(sR[e] + br);
        float z = sigmf(sZ[e] + bz);
        float n = tanhf(sNI[e] + bni + r * (sNH[e] + bnh));
        float hp = hinT[(size_t)j * Bz + b];
        houtT[(size_t)j * Bz + b] = (1.0f - z) * n + z * hp;
    }
}

// ---------------------------------------------------------------------------
// houts: C[64 b x 8 cols] over 1024 virtual cols (512 out + 512 sel),
// K = 1024, 8-warp K-split, direct global->register fragments, 3xTF32.
// Sel blocks fuse the Bernoulli mask epilogue.
// ---------------------------------------------------------------------------
__global__ __launch_bounds__(256) void houts_kernel(
    int t,
    const float* __restrict__ Wout, const float* __restrict__ bout,
    const float* __restrict__ Wsel, const float* __restrict__ bsel,
    const float* __restrict__ x, const float* __restrict__ u,
    float* __restrict__ out, float* __restrict__ selw)
{
    __shared__ float Cred[8 * 576];      // [8][64][9]

    const float* __restrict__ hT = g_hT[(t + 1) & 1];

    const int tid  = threadIdx.x;
    const int w    = tid >> 5;
    const int lane = tid & 31;
    const int g    = lane >> 2;
    const int tig  = lane & 3;
    const int c0   = blockIdx.x * 8;

    // lane's B-fragment row = output column c0 + g
    const int cc = c0 + g;
    const float* __restrict__ wrow = (cc < Oz) ? (Wout + (size_t)cc * Hz)
                                               : (Wsel + (size_t)(cc - Oz) * Hz);

    float acc[4][4] = {};
    float araw[4][4];
    float wraw[2];

    auto loadRaw = [&](int c) {
        int kg = (c * 8 + w) * 8;
        const float* r0 = hT + (size_t)(kg + tig) * Bz;
        const float* r1 = hT + (size_t)(kg + tig + 4) * Bz;
        #pragma unroll
        for (int mf = 0; mf < 4; mf++) {
            araw[mf][0] = r0[mf * 16 + g];
            araw[mf][1] = r0[mf * 16 + 8 + g];
            araw[mf][2] = r1[mf * 16 + g];
            araw[mf][3] = r1[mf * 16 + 8 + g];
        }
        wraw[0] = wrow[kg + tig];
        wraw[1] = wrow[kg + tig + 4];
    };

    loadRaw(0);
    for (int c = 0; c < 16; c++) {
        unsigned afh[4][4], afl[4][4], bfh[2], bfl[2];
        #pragma unroll
        for (int mf = 0; mf < 4; mf++)
            #pragma unroll
            for (int i = 0; i < 4; i++)
                split_mask(araw[mf][i], afh[mf][i], afl[mf][i]);
        split_mask(wraw[0], bfh[0], bfl[0]);
        split_mask(wraw[1], bfh[1], bfl[1]);
        if (c + 1 < 16) loadRaw(c + 1);
        #pragma unroll
        for (int mf = 0; mf < 4; mf++) {
            mma_tf32(acc[mf], afh[mf], bfh);
            mma_tf32(acc[mf], afh[mf], bfl);
            mma_tf32(acc[mf], afl[mf], bfh);
        }
    }

    // ---- epilogue: 8-way reduction, then out-write or fused mask ----
    #pragma unroll
    for (int mf = 0; mf < 4; mf++) {
        const float* d = acc[mf];
        int base = w * 576 + (mf * 16 + g) * 9 + 2 * tig;
        Cred[base] = d[0];      Cred[base + 1] = d[1];
        Cred[base + 72] = d[2]; Cred[base + 73] = d[3];
    }
    __syncthreads();

    int cnt = 0;
    #pragma unroll
    for (int e = 0; e < 2; e++) {
        int pid = tid + e * 256;
        int b = pid & 63, cl = pid >> 6;
        float s = 0.f;
        #pragma unroll
        for (int w8 = 0; w8 < 8; w8++) s += Cred[w8 * 576 + b * 9 + cl];
        int c = c0 + cl;
        if (c < Oz) {
            out[(size_t)t * Bz * Oz + (size_t)b * Oz + c] = s + bout[c];
        } else if (t < Tz - 1) {
            int f = c - Oz;
            float lg = s + bsel[f];
            float sg = sigmf(lg);
            float uu = u[((size_t)(t + 1) * Bz + b) * Fz + f];
            float wv = (sg > uu) ? 1.0f : 0.0f;
            selw[((size_t)(t + 1) * Bz + b) * Fz + f] = wv;
            cnt += (int)wv;
            g_cinT[f * Bz + b] = wv * x[((size_t)b * Tz + t + 1) * Fz + f];
        }
    }
    #pragma unroll
    for (int o = 16; o; o >>= 1) cnt += __shfl_down_sync(0xffffffffu, cnt, o);
    if ((tid & 31) == 0 && cnt) atomicAdd(&g_nsel, cnt);
}

// ---------------------------------------------------------------------------
__global__ void finalize_kernel(float* __restrict__ out) {
    out[(size_t)Tz * Bz * Oz] = (float)g_nsel;
}

// ---------------------------------------------------------------------------
extern "C" void kernel_launch(void* const* d_in, const int* in_sizes, int n_in,
                              void* d_out, int out_size) {
    const float* x    = (const float*)d_in[0];
    const float* u    = (const float*)d_in[1];
    const float* Wih  = (const float*)d_in[2];
    const float* bih  = (const float*)d_in[3];
    const float* Whh  = (const float*)d_in[4];
    const float* bhh  = (const float*)d_in[5];
    const float* Wout = (const float*)d_in[6];
    const float* bout = (const float*)d_in[7];
    const float* Wsel = (const float*)d_in[8];
    const float* bsel = (const float*)d_in[9];

    float* out  = (float*)d_out;
    float* selw = out + (size_t)Tz * Bz * Oz + 1;

    cudaFuncSetAttribute(gates_kernel, cudaFuncAttributeMaxDynamicSharedMemorySize, GATES_SMEM);

    init_kernel<<<(Hz * Bz + 255) / 256, 256>>>(x, selw);
    for (int t = 0; t < Tz; t++) {
        gates_kernel<<<128, 256, GATES_SMEM>>>(t, Wih, bih, Whh, bhh);
        houts_kernel<<<128, 256>>>(t, Wout, bout, Wsel, bsel, x, u, out, selw);
    }
    finalize_kernel<<<1, 1>>>(out);
}